// round 13
// baseline (speedup 1.0000x reference)
#include <cuda_runtime.h>
#include <math.h>

// Hybrid-precision batched expm of sl(3) elements.
//   Pass 1 (fp32, PACKED f32x2): two batch items per thread via fma.rn.f32x2.
//     Fixed scaling s=3, PS degree-11 Taylor, 3 squarings. Flags untrusted
//     samples via warp-aggregated atomics. Smem-staged float4 coalesced stores.
//   Pass 2 (df64, 9-LANE COOPERATIVE): one matrix element per lane, 3 items
//     per warp, shuffle-based 3x3 df64 matmuls, fixed s=5, straight-line.

#define MAXB (1 << 20)
#define TAU 262144.0f
__device__ int g_count;
__device__ int g_flag_idx[MAXB];

typedef unsigned long long u64;

// ---------------- packed f32x2 helpers (pass 1) ----------------
__device__ __forceinline__ u64 pk2(float lo, float hi) {
    u64 r;
    asm("mov.b64 %0, {%1, %2};" : "=l"(r) : "f"(lo), "f"(hi));
    return r;
}
__device__ __forceinline__ void upk2(u64 v, float& lo, float& hi) {
    asm("mov.b64 {%0, %1}, %2;" : "=f"(lo), "=f"(hi) : "l"(v));
}
__device__ __forceinline__ u64 fma2(u64 a, u64 b, u64 c) {
    u64 d;
    asm("fma.rn.f32x2 %0, %1, %2, %3;" : "=l"(d) : "l"(a), "l"(b), "l"(c));
    return d;
}
__device__ __forceinline__ u64 mul2(u64 a, u64 b) {
    u64 d;
    asm("mul.rn.f32x2 %0, %1, %2;" : "=l"(d) : "l"(a), "l"(b));
    return d;
}
__device__ __forceinline__ u64 add2(u64 a, u64 b) {
    u64 d;
    asm("add.rn.f32x2 %0, %1, %2;" : "=l"(d) : "l"(a), "l"(b));
    return d;
}

__device__ __forceinline__ void mm3p(const u64* __restrict__ a,
                                     const u64* __restrict__ b,
                                     u64* __restrict__ c) {
#pragma unroll
    for (int i = 0; i < 3; i++)
#pragma unroll
        for (int j = 0; j < 3; j++) {
            u64 s = mul2(a[i * 3], b[j]);
            s = fma2(a[i * 3 + 1], b[3 + j], s);
            s = fma2(a[i * 3 + 2], b[6 + j], s);
            c[i * 3 + j] = s;
        }
}

// ---------------- df64 (double-float) arithmetic (pass 2) ----------------
struct df { float h, l; };

__device__ __forceinline__ df two_sum(float a, float b) {
    float s = a + b;
    float bb = s - a;
    float e = (a - (s - bb)) + (b - bb);
    df r; r.h = s; r.l = e; return r;
}
__device__ __forceinline__ df quick2(float a, float b) {  // |a| >= |b|
    float s = a + b;
    float e = b - (s - a);
    df r; r.h = s; r.l = e; return r;
}
__device__ __forceinline__ df df_add(df a, df b) {
    df s = two_sum(a.h, b.h);
    s.l += (a.l + b.l);
    return quick2(s.h, s.l);
}
__device__ __forceinline__ df df_mul(df a, df b) {
    float p = a.h * b.h;
    float e = fmaf(a.h, b.h, -p);
    e = fmaf(a.h, b.l, fmaf(a.l, b.h, e));
    return quick2(p, e);
}
__device__ __forceinline__ df df_scale_pow2(df a, float p2) {
    df r; r.h = a.h * p2; r.l = a.l * p2; return r;
}
__device__ __forceinline__ df df_neg(df a) { df r; r.h = -a.h; r.l = -a.l; return r; }

#define DFC(x) df{(float)(x), (float)((x) - (double)(float)(x))}

// Compensated 3-term df dot product.
__device__ __forceinline__ df dot3(df a0, df b0, df a1, df b1, df a2, df b2) {
    float p1 = a0.h * b0.h;
    float e1 = fmaf(a0.h, b0.h, -p1);
    e1 = fmaf(a0.h, b0.l, fmaf(a0.l, b0.h, e1));
    float p2 = a1.h * b1.h;
    float e2 = fmaf(a1.h, b1.h, -p2);
    e2 = fmaf(a1.h, b1.l, fmaf(a1.l, b1.h, e2));
    float p3 = a2.h * b2.h;
    float e3 = fmaf(a2.h, b2.h, -p3);
    e3 = fmaf(a2.h, b2.l, fmaf(a2.l, b2.h, e3));

    df s1 = two_sum(p1, p2);
    df s2 = two_sum(s1.h, p3);
    float e = ((e1 + e2) + (e3 + s1.l)) + s2.l;
    return quick2(s2.h, e);
}

__device__ __forceinline__ df shfl_df(df v, int src) {
    df r;
    r.h = __shfl_sync(0xFFFFFFFFu, v.h, src);
    r.l = __shfl_sync(0xFFFFFFFFu, v.l, src);
    return r;
}

// 9-lane cooperative 3x3 df matmul. Lane holds element (i,j). Returns my
// element of X*Y given my elements xv (of X) and yv (of Y).
__device__ __forceinline__ df coop9_mm(df xv, df yv, int gbase, int i3, int j) {
    df X0 = shfl_df(xv, gbase + i3);
    df X1 = shfl_df(xv, gbase + i3 + 1);
    df X2 = shfl_df(xv, gbase + i3 + 2);
    df Y0 = shfl_df(yv, gbase + j);
    df Y1 = shfl_df(yv, gbase + 3 + j);
    df Y2 = shfl_df(yv, gbase + 6 + j);
    return dot3(X0, Y0, X1, Y1, X2, Y2);
}

__global__ void __launch_bounds__(64)
pass2_coop9_kernel(const float* __restrict__ lie, float* __restrict__ out) {
    int cnt = g_count;
    if (cnt > MAXB) cnt = MAXB;

    int lane = threadIdx.x & 31;
    int grp = lane / 9;            // 0..2 active groups; grp==3 (lanes 27-31) idle
    int e = lane - grp * 9;        // element index 0..8
    int i = e / 3, j = e - 3 * (e / 3);
    int i3 = 3 * i;
    int gbase = grp * 9;
    bool grp_ok = (grp < 3);

    int wpb = blockDim.x >> 5;
    int gwarp = blockIdx.x * wpb + (threadIdx.x >> 5);
    int nwarp = gridDim.x * wpb;

    for (int it0 = gwarp * 3; it0 < cnt; it0 += nwarp * 3) {
        int item = it0 + grp;
        bool active = grp_ok && (item < cnt);
        int idx = active ? g_flag_idx[item] : 0;

        const float4* vp = reinterpret_cast<const float4*>(lie) + 2 * (size_t)idx;
        float4 v0 = vp[0];
        float4 v1 = vp[1];
        float x = v0.x, y = v0.y, r = v0.z, sc = v0.w;
        float st = v1.x, sh = v1.y, kx = v1.z, ky = v1.w;

        // My element of A (exact df), selected by e.
        float u, w;
        switch (e) {
            case 0: u = sc; w = st;  break;
            case 1: u = sh; w = -r;  break;
            case 2: u = x;  w = 0.f; break;
            case 3: u = sh; w = r;   break;
            case 4: u = sc; w = -st; break;
            case 5: u = y;  w = 0.f; break;
            case 6: u = kx; w = 0.f; break;
            case 7: u = ky; w = 0.f; break;
            default: u = -2.0f * sc; w = 0.f; break;
        }
        const float SCL = 0.03125f;  // 2^-5, fixed s = 5 (nrm <= 32 guaranteed)
        df A = df_scale_pow2(two_sum(u, w), SCL);

        df A2 = coop9_mm(A, A, gbase, i3, j);
        df A3 = coop9_mm(A2, A, gbase, i3, j);

        const df C2  = DFC(1.0 / 2.0);
        const df C3  = DFC(1.0 / 6.0);
        const df C4  = DFC(1.0 / 24.0);
        const df C5  = DFC(1.0 / 120.0);
        const df C6  = DFC(1.0 / 720.0);
        const df C7  = DFC(1.0 / 5040.0);
        const df C8  = DFC(1.0 / 40320.0);
        const df C9  = DFC(1.0 / 362880.0);
        const df C10 = DFC(1.0 / 3628800.0);
        const df C11 = DFC(1.0 / 39916800.0);
        bool diag = (i == j);

        // P = c9*I + c10*A + c11*A2
        df P = df_add(df_mul(C10, A), df_mul(C11, A2));
        if (diag) P = df_add(P, C9);

        // P = P*A3 + c6*I + c7*A + c8*A2
        P = coop9_mm(P, A3, gbase, i3, j);
        P = df_add(P, df_add(df_mul(C7, A), df_mul(C8, A2)));
        if (diag) P = df_add(P, C6);

        // P = P*A3 + c3*I + c4*A + c5*A2
        P = coop9_mm(P, A3, gbase, i3, j);
        P = df_add(P, df_add(df_mul(C4, A), df_mul(C5, A2)));
        if (diag) P = df_add(P, C3);

        // P = P*A3 + I + A + c2*A2
        P = coop9_mm(P, A3, gbase, i3, j);
        P = df_add(P, df_add(A, df_mul(C2, A2)));
        if (diag) P = df_add(P, df{1.0f, 0.0f});

        // Exactly 5 squarings.
#pragma unroll
        for (int q = 0; q < 5; q++)
            P = coop9_mm(P, P, gbase, i3, j);

        // H22 lives in lane gbase+8.
        df p22 = shfl_df(P, gbase + 8);

        float approx = 1.0f / p22.h;
        df err = df_mul(p22, df{approx, 0.f});
        df corr = df_add(df{2.0f, 0.0f}, df_neg(err));
        df rcp = df_mul(corr, df{approx, 0.f});

        if (active) {
            df qv = df_mul(P, rcp);
            out[9 * (size_t)idx + e] = qv.h + qv.l;
        }
    }
}

// ---------------- fp32 packed fast path ----------------
__global__ void __launch_bounds__(128)
pass1_f32x2_kernel(const float* __restrict__ lie, float* __restrict__ out, int n) {
    __shared__ __align__(16) float stage[128 * 18];

    int t = blockIdx.x * blockDim.x + threadIdx.x;
    int lane = threadIdx.x & 31;
    int warp = threadIdx.x >> 5;
    long long i0 = 2LL * t;
    long long i1 = i0 + 1;
    bool vlo = (i0 < n), vhi = (i1 < n);

    float4 a0 = make_float4(0.f, 0.f, 0.f, 0.f), a1 = a0, b0 = a0, b1 = a0;
    if (vlo) {
        const float4* vp = reinterpret_cast<const float4*>(lie) + 2 * i0;
        a0 = vp[0]; a1 = vp[1];
    }
    if (vhi) {
        const float4* vp = reinterpret_cast<const float4*>(lie) + 2 * i1;
        b0 = vp[0]; b1 = vp[1];
    }

    const float SCL = 0.125f;  // fixed s = 3

    float AL[9], AH[9];
    AL[0] = (a0.w + a1.x) * SCL; AL[1] = (a1.y - a0.z) * SCL; AL[2] = a0.x * SCL;
    AL[3] = (a1.y + a0.z) * SCL; AL[4] = (a0.w - a1.x) * SCL; AL[5] = a0.y * SCL;
    AL[6] = a1.z * SCL;          AL[7] = a1.w * SCL;          AL[8] = -2.0f * a0.w * SCL;

    AH[0] = (b0.w + b1.x) * SCL; AH[1] = (b1.y - b0.z) * SCL; AH[2] = b0.x * SCL;
    AH[3] = (b1.y + b0.z) * SCL; AH[4] = (b0.w - b1.x) * SCL; AH[5] = b0.y * SCL;
    AH[6] = b1.z * SCL;          AH[7] = b1.w * SCL;          AH[8] = -2.0f * b0.w * SCL;

    float nl = fmaxf(fabsf(AL[0]) + fabsf(AL[1]) + fabsf(AL[2]),
               fmaxf(fabsf(AL[3]) + fabsf(AL[4]) + fabsf(AL[5]),
                     fabsf(AL[6]) + fabsf(AL[7]) + fabsf(AL[8])));
    float nh = fmaxf(fabsf(AH[0]) + fabsf(AH[1]) + fabsf(AH[2]),
               fmaxf(fabsf(AH[3]) + fabsf(AH[4]) + fabsf(AH[5]),
                     fabsf(AH[6]) + fabsf(AH[7]) + fabsf(AH[8])));

    u64 A[9];
#pragma unroll
    for (int k = 0; k < 9; k++) A[k] = pk2(AL[k], AH[k]);

    u64 A2[9], A3[9];
    mm3p(A, A, A2);
    mm3p(A2, A, A3);

    const u64 C2  = pk2(1.0f / 2, 1.0f / 2);
    const u64 C3  = pk2(1.0f / 6, 1.0f / 6);
    const u64 C4  = pk2(1.0f / 24, 1.0f / 24);
    const u64 C5  = pk2(1.0f / 120, 1.0f / 120);
    const u64 C6  = pk2(1.0f / 720, 1.0f / 720);
    const u64 C7  = pk2(1.0f / 5040, 1.0f / 5040);
    const u64 C8  = pk2(1.0f / 40320, 1.0f / 40320);
    const u64 C9  = pk2(1.0f / 362880, 1.0f / 362880);
    const u64 C10 = pk2(1.0f / 3628800, 1.0f / 3628800);
    const u64 C11 = pk2(1.0f / 39916800, 1.0f / 39916800);
    const u64 ONE = pk2(1.0f, 1.0f);

    u64 P[9], T[9];
#pragma unroll
    for (int k = 0; k < 9; k++) P[k] = fma2(C10, A[k], mul2(C11, A2[k]));
    P[0] = add2(P[0], C9); P[4] = add2(P[4], C9); P[8] = add2(P[8], C9);

    mm3p(P, A3, T);
#pragma unroll
    for (int k = 0; k < 9; k++) P[k] = fma2(C7, A[k], fma2(C8, A2[k], T[k]));
    P[0] = add2(P[0], C6); P[4] = add2(P[4], C6); P[8] = add2(P[8], C6);

    mm3p(P, A3, T);
#pragma unroll
    for (int k = 0; k < 9; k++) P[k] = fma2(C4, A[k], fma2(C5, A2[k], T[k]));
    P[0] = add2(P[0], C3); P[4] = add2(P[4], C3); P[8] = add2(P[8], C3);

    mm3p(P, A3, T);
#pragma unroll
    for (int k = 0; k < 9; k++) P[k] = fma2(C2, A2[k], add2(T[k], A[k]));
    P[0] = add2(P[0], ONE); P[4] = add2(P[4], ONE); P[8] = add2(P[8], ONE);

    mm3p(P, P, T);
    mm3p(T, T, P);
    mm3p(P, P, T);

    float HL[9], HH[9];
#pragma unroll
    for (int k = 0; k < 9; k++) upk2(T[k], HL[k], HH[k]);

    float mxl = 0.0f, mxh = 0.0f;
#pragma unroll
    for (int k = 0; k < 9; k++) {
        mxl = fmaxf(mxl, fabsf(HL[k]));
        mxh = fmaxf(mxh, fabsf(HH[k]));
    }
    bool flag_lo = vlo && !((nl <= 2.0f) && (8.0f * mxl <= TAU * fabsf(HL[8])));
    bool flag_hi = vhi && !((nh <= 2.0f) && (8.0f * mxh <= TAU * fabsf(HH[8])));

    unsigned blo = __ballot_sync(0xFFFFFFFFu, flag_lo);
    if (blo) {
        int leader = __ffs(blo) - 1;
        int base = 0;
        if (lane == leader) base = atomicAdd(&g_count, __popc(blo));
        base = __shfl_sync(0xFFFFFFFFu, base, leader);
        if (flag_lo) {
            int slot = base + __popc(blo & ((1u << lane) - 1u));
            if (slot < MAXB) g_flag_idx[slot] = (int)i0;
        }
    }
    unsigned bhi = __ballot_sync(0xFFFFFFFFu, flag_hi);
    if (bhi) {
        int leader = __ffs(bhi) - 1;
        int base = 0;
        if (lane == leader) base = atomicAdd(&g_count, __popc(bhi));
        base = __shfl_sync(0xFFFFFFFFu, base, leader);
        if (flag_hi) {
            int slot = base + __popc(bhi & ((1u << lane) - 1u));
            if (slot < MAXB) g_flag_idx[slot] = (int)i1;
        }
    }

    float invl = 1.0f / HL[8];
    float invh = 1.0f / HH[8];
    float* ws = stage + warp * 576;
#pragma unroll
    for (int k = 0; k < 9; k++) {
        ws[lane * 18 + k] = HL[k] * invl;
        ws[lane * 18 + 9 + k] = HH[k] * invh;
    }
    __syncwarp();

    long long wstart = 2LL * ((long long)blockIdx.x * blockDim.x + warp * 32);
    long long rem = (long long)n - wstart;
    if (rem >= 64) {
        // Full warp: 576 floats = 144 float4, both sides 16B-aligned.
        float4* o4 = reinterpret_cast<float4*>(out + 9 * wstart);
        const float4* s4 = reinterpret_cast<const float4*>(ws);
#pragma unroll
        for (int j = lane; j < 144; j += 32) o4[j] = s4[j];
    } else if (rem > 0) {
        int vcount = (int)rem;
        float* o = out + 9 * wstart;
        int total = vcount * 9;
        for (int j = lane; j < total; j += 32) o[j] = ws[j];
    }
}

extern "C" void kernel_launch(void* const* d_in, const int* in_sizes, int n_in,
                              void* d_out, int out_size) {
    const float* lie = (const float*)d_in[0];
    float* out = (float*)d_out;
    int n = in_sizes[0] / 8;

    void* cnt_addr = nullptr;
    cudaGetSymbolAddress(&cnt_addr, g_count);
    cudaMemsetAsync(cnt_addr, 0, sizeof(int));

    int threads = 128;
    int items_per_block = threads * 2;
    int blocks = (n + items_per_block - 1) / items_per_block;
    pass1_f32x2_kernel<<<blocks, threads>>>(lie, out, n);
    pass2_coop9_kernel<<<2048, 64>>>(lie, out);
}

// round 14
// speedup vs baseline: 1.3351x; 1.3351x over previous
#include <cuda_runtime.h>
#include <math.h>

// Hybrid-precision batched expm of sl(3) elements.
//   Pass 1 (fp32, PACKED f32x2): two batch items per thread via fma.rn.f32x2.
//     Fixed scaling s=3, PS degree-11 Taylor, 3 squarings. Flags untrusted
//     samples via warp-aggregated atomics (single atomic per warp).
//     Smem-staged scalar coalesced stores. rcp.approx for normalization.
//   Pass 2 (df64, 3-lane cooperative): one matrix row per lane, shuffle-based
//     3x3 df64 matmuls, fixed s=5, straight-line.

#define MAXB (1 << 20)
#define TAU 262144.0f
__device__ int g_count;
__device__ int g_flag_idx[MAXB];

typedef unsigned long long u64;

// ---------------- packed f32x2 helpers (pass 1) ----------------
__device__ __forceinline__ u64 pk2(float lo, float hi) {
    u64 r;
    asm("mov.b64 %0, {%1, %2};" : "=l"(r) : "f"(lo), "f"(hi));
    return r;
}
__device__ __forceinline__ void upk2(u64 v, float& lo, float& hi) {
    asm("mov.b64 {%0, %1}, %2;" : "=f"(lo), "=f"(hi) : "l"(v));
}
__device__ __forceinline__ u64 fma2(u64 a, u64 b, u64 c) {
    u64 d;
    asm("fma.rn.f32x2 %0, %1, %2, %3;" : "=l"(d) : "l"(a), "l"(b), "l"(c));
    return d;
}
__device__ __forceinline__ u64 mul2(u64 a, u64 b) {
    u64 d;
    asm("mul.rn.f32x2 %0, %1, %2;" : "=l"(d) : "l"(a), "l"(b));
    return d;
}
__device__ __forceinline__ u64 add2(u64 a, u64 b) {
    u64 d;
    asm("add.rn.f32x2 %0, %1, %2;" : "=l"(d) : "l"(a), "l"(b));
    return d;
}
__device__ __forceinline__ float frcp_approx(float x) {
    float r;
    asm("rcp.approx.f32 %0, %1;" : "=f"(r) : "f"(x));
    return r;
}

__device__ __forceinline__ void mm3p(const u64* __restrict__ a,
                                     const u64* __restrict__ b,
                                     u64* __restrict__ c) {
#pragma unroll
    for (int i = 0; i < 3; i++)
#pragma unroll
        for (int j = 0; j < 3; j++) {
            u64 s = mul2(a[i * 3], b[j]);
            s = fma2(a[i * 3 + 1], b[3 + j], s);
            s = fma2(a[i * 3 + 2], b[6 + j], s);
            c[i * 3 + j] = s;
        }
}

// ---------------- df64 (double-float) arithmetic (pass 2) ----------------
struct df { float h, l; };

__device__ __forceinline__ df two_sum(float a, float b) {
    float s = a + b;
    float bb = s - a;
    float e = (a - (s - bb)) + (b - bb);
    df r; r.h = s; r.l = e; return r;
}
__device__ __forceinline__ df quick2(float a, float b) {  // |a| >= |b|
    float s = a + b;
    float e = b - (s - a);
    df r; r.h = s; r.l = e; return r;
}
__device__ __forceinline__ df df_add(df a, df b) {
    df s = two_sum(a.h, b.h);
    s.l += (a.l + b.l);
    return quick2(s.h, s.l);
}
__device__ __forceinline__ df df_mul(df a, df b) {
    float p = a.h * b.h;
    float e = fmaf(a.h, b.h, -p);
    e = fmaf(a.h, b.l, fmaf(a.l, b.h, e));
    return quick2(p, e);
}
__device__ __forceinline__ df df_scale_pow2(df a, float p2) {
    df r; r.h = a.h * p2; r.l = a.l * p2; return r;
}
__device__ __forceinline__ df df_neg(df a) { df r; r.h = -a.h; r.l = -a.l; return r; }

#define DFC(x) df{(float)(x), (float)((x) - (double)(float)(x))}

// Compensated 3-term df dot product.
__device__ __forceinline__ df dot3(df a0, df b0, df a1, df b1, df a2, df b2) {
    float p1 = a0.h * b0.h;
    float e1 = fmaf(a0.h, b0.h, -p1);
    e1 = fmaf(a0.h, b0.l, fmaf(a0.l, b0.h, e1));
    float p2 = a1.h * b1.h;
    float e2 = fmaf(a1.h, b1.h, -p2);
    e2 = fmaf(a1.h, b1.l, fmaf(a1.l, b1.h, e2));
    float p3 = a2.h * b2.h;
    float e3 = fmaf(a2.h, b2.h, -p3);
    e3 = fmaf(a2.h, b2.l, fmaf(a2.l, b2.h, e3));

    df s1 = two_sum(p1, p2);
    df s2 = two_sum(s1.h, p3);
    float e = ((e1 + e2) + (e3 + s1.l)) + s2.l;
    return quick2(s2.h, e);
}

__device__ __forceinline__ df shfl_df(df v, int src) {
    df r;
    r.h = __shfl_sync(0xFFFFFFFFu, v.h, src);
    r.l = __shfl_sync(0xFFFFFFFFu, v.l, src);
    return r;
}

// Cooperative 3x3 df matmul: 3 lanes per item, lane holds one row.
__device__ __forceinline__ void coop_mm(df& c0, df& c1, df& c2,
                                        df a0, df a1, df a2,
                                        df y0, df y1, df y2, int base) {
    df Y00 = shfl_df(y0, base),     Y01 = shfl_df(y1, base),     Y02 = shfl_df(y2, base);
    df Y10 = shfl_df(y0, base + 1), Y11 = shfl_df(y1, base + 1), Y12 = shfl_df(y2, base + 1);
    df Y20 = shfl_df(y0, base + 2), Y21 = shfl_df(y1, base + 2), Y22 = shfl_df(y2, base + 2);
    c0 = dot3(a0, Y00, a1, Y10, a2, Y20);
    c1 = dot3(a0, Y01, a1, Y11, a2, Y21);
    c2 = dot3(a0, Y02, a1, Y12, a2, Y22);
}

__device__ __forceinline__ void expm_coop(const float* __restrict__ lie,
                                          float* __restrict__ out,
                                          int idx, int role, int base,
                                          bool active) {
    const float4* vp = reinterpret_cast<const float4*>(lie) + 2 * (size_t)idx;
    float4 v0 = vp[0];
    float4 v1 = vp[1];
    float x = v0.x, y = v0.y, r = v0.z, sc = v0.w;
    float st = v1.x, sh = v1.y, kx = v1.z, ky = v1.w;

    float u0, w0, u1, w1, u2, w2;
    if (role == 0)      { u0 = sc; w0 = st;  u1 = sh; w1 = -r;  u2 = x;           w2 = 0.f; }
    else if (role == 1) { u0 = sh; w0 = r;   u1 = sc; w1 = -st; u2 = y;           w2 = 0.f; }
    else                { u0 = kx; w0 = 0.f; u1 = ky; w1 = 0.f; u2 = -2.0f * sc;  w2 = 0.f; }

    const float SCL = 0.03125f;  // 2^-5 (fixed s = 5; nrm <= 32 guaranteed)
    df A0 = df_scale_pow2(two_sum(u0, w0), SCL);
    df A1 = df_scale_pow2(two_sum(u1, w1), SCL);
    df A2 = df_scale_pow2(two_sum(u2, w2), SCL);

    df B0, B1, B2;  // row of A^2
    coop_mm(B0, B1, B2, A0, A1, A2, A0, A1, A2, base);
    df Z0, Z1, Z2;  // row of A^3
    coop_mm(Z0, Z1, Z2, B0, B1, B2, A0, A1, A2, base);

    const df C2  = DFC(1.0 / 2.0);
    const df C3  = DFC(1.0 / 6.0);
    const df C4  = DFC(1.0 / 24.0);
    const df C5  = DFC(1.0 / 120.0);
    const df C6  = DFC(1.0 / 720.0);
    const df C7  = DFC(1.0 / 5040.0);
    const df C8  = DFC(1.0 / 40320.0);
    const df C9  = DFC(1.0 / 362880.0);
    const df C10 = DFC(1.0 / 3628800.0);
    const df C11 = DFC(1.0 / 39916800.0);
    const df ONE = df{1.0f, 0.0f};

    df P0, P1, P2, T0, T1, T2;

    P0 = df_add(df_mul(C10, A0), df_mul(C11, B0));
    P1 = df_add(df_mul(C10, A1), df_mul(C11, B1));
    P2 = df_add(df_mul(C10, A2), df_mul(C11, B2));
    if (role == 0) P0 = df_add(P0, C9);
    else if (role == 1) P1 = df_add(P1, C9);
    else P2 = df_add(P2, C9);

    coop_mm(T0, T1, T2, P0, P1, P2, Z0, Z1, Z2, base);
    P0 = df_add(T0, df_add(df_mul(C7, A0), df_mul(C8, B0)));
    P1 = df_add(T1, df_add(df_mul(C7, A1), df_mul(C8, B1)));
    P2 = df_add(T2, df_add(df_mul(C7, A2), df_mul(C8, B2)));
    if (role == 0) P0 = df_add(P0, C6);
    else if (role == 1) P1 = df_add(P1, C6);
    else P2 = df_add(P2, C6);

    coop_mm(T0, T1, T2, P0, P1, P2, Z0, Z1, Z2, base);
    P0 = df_add(T0, df_add(df_mul(C4, A0), df_mul(C5, B0)));
    P1 = df_add(T1, df_add(df_mul(C4, A1), df_mul(C5, B1)));
    P2 = df_add(T2, df_add(df_mul(C4, A2), df_mul(C5, B2)));
    if (role == 0) P0 = df_add(P0, C3);
    else if (role == 1) P1 = df_add(P1, C3);
    else P2 = df_add(P2, C3);

    coop_mm(T0, T1, T2, P0, P1, P2, Z0, Z1, Z2, base);
    P0 = df_add(T0, df_add(A0, df_mul(C2, B0)));
    P1 = df_add(T1, df_add(A1, df_mul(C2, B1)));
    P2 = df_add(T2, df_add(A2, df_mul(C2, B2)));
    if (role == 0) P0 = df_add(P0, ONE);
    else if (role == 1) P1 = df_add(P1, ONE);
    else P2 = df_add(P2, ONE);

#pragma unroll
    for (int q = 0; q < 5; q++) {
        coop_mm(T0, T1, T2, P0, P1, P2, P0, P1, P2, base);
        P0 = T0; P1 = T1; P2 = T2;
    }

    df p22 = shfl_df(P2, base + 2);

    float approx = frcp_approx(p22.h);
    df e = df_mul(p22, df{approx, 0.f});
    df corr = df_add(df{2.0f, 0.0f}, df_neg(e));
    df rcp = df_mul(corr, df{approx, 0.f});

    if (active) {
        float* o = out + 9 * (size_t)idx + 3 * role;
        df q0 = df_mul(P0, rcp);
        df q1 = df_mul(P1, rcp);
        df q2 = df_mul(P2, rcp);
        o[0] = q0.h + q0.l;
        o[1] = q1.h + q1.l;
        o[2] = q2.h + q2.l;
    }
}

// ---------------- fp32 packed fast path ----------------
__global__ void __launch_bounds__(128)
pass1_f32x2_kernel(const float* __restrict__ lie, float* __restrict__ out, int n) {
    __shared__ float stage[128 * 18];

    int t = blockIdx.x * blockDim.x + threadIdx.x;
    int lane = threadIdx.x & 31;
    int warp = threadIdx.x >> 5;
    long long i0 = 2LL * t;
    long long i1 = i0 + 1;
    bool vlo = (i0 < n), vhi = (i1 < n);

    float4 a0 = make_float4(0.f, 0.f, 0.f, 0.f), a1 = a0, b0 = a0, b1 = a0;
    if (vlo) {
        const float4* vp = reinterpret_cast<const float4*>(lie) + 2 * i0;
        a0 = vp[0]; a1 = vp[1];
    }
    if (vhi) {
        const float4* vp = reinterpret_cast<const float4*>(lie) + 2 * i1;
        b0 = vp[0]; b1 = vp[1];
    }

    const float SCL = 0.125f;  // fixed s = 3

    float AL[9], AH[9];
    AL[0] = (a0.w + a1.x) * SCL; AL[1] = (a1.y - a0.z) * SCL; AL[2] = a0.x * SCL;
    AL[3] = (a1.y + a0.z) * SCL; AL[4] = (a0.w - a1.x) * SCL; AL[5] = a0.y * SCL;
    AL[6] = a1.z * SCL;          AL[7] = a1.w * SCL;          AL[8] = -2.0f * a0.w * SCL;

    AH[0] = (b0.w + b1.x) * SCL; AH[1] = (b1.y - b0.z) * SCL; AH[2] = b0.x * SCL;
    AH[3] = (b1.y + b0.z) * SCL; AH[4] = (b0.w - b1.x) * SCL; AH[5] = b0.y * SCL;
    AH[6] = b1.z * SCL;          AH[7] = b1.w * SCL;          AH[8] = -2.0f * b0.w * SCL;

    float nl = fmaxf(fabsf(AL[0]) + fabsf(AL[1]) + fabsf(AL[2]),
               fmaxf(fabsf(AL[3]) + fabsf(AL[4]) + fabsf(AL[5]),
                     fabsf(AL[6]) + fabsf(AL[7]) + fabsf(AL[8])));
    float nh = fmaxf(fabsf(AH[0]) + fabsf(AH[1]) + fabsf(AH[2]),
               fmaxf(fabsf(AH[3]) + fabsf(AH[4]) + fabsf(AH[5]),
                     fabsf(AH[6]) + fabsf(AH[7]) + fabsf(AH[8])));

    u64 A[9];
#pragma unroll
    for (int k = 0; k < 9; k++) A[k] = pk2(AL[k], AH[k]);

    u64 A2[9], A3[9];
    mm3p(A, A, A2);
    mm3p(A2, A, A3);

    const u64 C2  = pk2(1.0f / 2, 1.0f / 2);
    const u64 C3  = pk2(1.0f / 6, 1.0f / 6);
    const u64 C4  = pk2(1.0f / 24, 1.0f / 24);
    const u64 C5  = pk2(1.0f / 120, 1.0f / 120);
    const u64 C6  = pk2(1.0f / 720, 1.0f / 720);
    const u64 C7  = pk2(1.0f / 5040, 1.0f / 5040);
    const u64 C8  = pk2(1.0f / 40320, 1.0f / 40320);
    const u64 C9  = pk2(1.0f / 362880, 1.0f / 362880);
    const u64 C10 = pk2(1.0f / 3628800, 1.0f / 3628800);
    const u64 C11 = pk2(1.0f / 39916800, 1.0f / 39916800);
    const u64 ONE = pk2(1.0f, 1.0f);

    u64 P[9], T[9];
#pragma unroll
    for (int k = 0; k < 9; k++) P[k] = fma2(C10, A[k], mul2(C11, A2[k]));
    P[0] = add2(P[0], C9); P[4] = add2(P[4], C9); P[8] = add2(P[8], C9);

    mm3p(P, A3, T);
#pragma unroll
    for (int k = 0; k < 9; k++) P[k] = fma2(C7, A[k], fma2(C8, A2[k], T[k]));
    P[0] = add2(P[0], C6); P[4] = add2(P[4], C6); P[8] = add2(P[8], C6);

    mm3p(P, A3, T);
#pragma unroll
    for (int k = 0; k < 9; k++) P[k] = fma2(C4, A[k], fma2(C5, A2[k], T[k]));
    P[0] = add2(P[0], C3); P[4] = add2(P[4], C3); P[8] = add2(P[8], C3);

    mm3p(P, A3, T);
#pragma unroll
    for (int k = 0; k < 9; k++) P[k] = fma2(C2, A2[k], add2(T[k], A[k]));
    P[0] = add2(P[0], ONE); P[4] = add2(P[4], ONE); P[8] = add2(P[8], ONE);

    mm3p(P, P, T);
    mm3p(T, T, P);
    mm3p(P, P, T);

    float HL[9], HH[9];
#pragma unroll
    for (int k = 0; k < 9; k++) upk2(T[k], HL[k], HH[k]);

    float mxl = 0.0f, mxh = 0.0f;
#pragma unroll
    for (int k = 0; k < 9; k++) {
        mxl = fmaxf(mxl, fabsf(HL[k]));
        mxh = fmaxf(mxh, fabsf(HH[k]));
    }
    bool flag_lo = vlo && !((nl <= 2.0f) && (8.0f * mxl <= TAU * fabsf(HL[8])));
    bool flag_hi = vhi && !((nh <= 2.0f) && (8.0f * mxh <= TAU * fabsf(HH[8])));

    // Warp-aggregated compaction: ONE atomic per warp for lo+hi combined.
    unsigned blo = __ballot_sync(0xFFFFFFFFu, flag_lo);
    unsigned bhi = __ballot_sync(0xFFFFFFFFu, flag_hi);
    if (blo | bhi) {
        int nlo = __popc(blo);
        int base = 0;
        if (lane == 0) base = atomicAdd(&g_count, nlo + __popc(bhi));
        base = __shfl_sync(0xFFFFFFFFu, base, 0);
        unsigned below = (1u << lane) - 1u;
        if (flag_lo) {
            int slot = base + __popc(blo & below);
            if (slot < MAXB) g_flag_idx[slot] = (int)i0;
        }
        if (flag_hi) {
            int slot = base + nlo + __popc(bhi & below);
            if (slot < MAXB) g_flag_idx[slot] = (int)i1;
        }
    }

    float invl = frcp_approx(HL[8]);
    float invh = frcp_approx(HH[8]);
    float* ws = stage + warp * 576;
#pragma unroll
    for (int k = 0; k < 9; k++) {
        ws[lane * 18 + k] = HL[k] * invl;
        ws[lane * 18 + 9 + k] = HH[k] * invh;
    }
    __syncwarp();

    long long wstart = 2LL * ((long long)blockIdx.x * blockDim.x + warp * 32);
    long long rem = (long long)n - wstart;
    int vcount = (rem > 64) ? 64 : (rem > 0 ? (int)rem : 0);
    if (vcount > 0) {
        float* o = out + 9 * wstart;
        int total = vcount * 9;
        for (int j = lane; j < total; j += 32) o[j] = ws[j];
    }
}

__global__ void __launch_bounds__(64)
pass2_coop_kernel(const float* __restrict__ lie, float* __restrict__ out) {
    int cnt = g_count;
    if (cnt > MAXB) cnt = MAXB;

    int lane = threadIdx.x & 31;
    int grp = lane / 3;            // 0..9 active groups; grp==10 idle (lanes 30,31)
    int role = lane - grp * 3;
    int base = grp * 3;

    int wpb = blockDim.x >> 5;
    int gwarp = blockIdx.x * wpb + (threadIdx.x >> 5);
    int nwarp = gridDim.x * wpb;

    for (int it0 = gwarp * 10; it0 < cnt; it0 += nwarp * 10) {
        int item = it0 + grp;
        bool active = (grp < 10) && (item < cnt);
        int idx = active ? g_flag_idx[item] : 0;
        expm_coop(lie, out, idx, role, base, active);
    }
}

extern "C" void kernel_launch(void* const* d_in, const int* in_sizes, int n_in,
                              void* d_out, int out_size) {
    const float* lie = (const float*)d_in[0];
    float* out = (float*)d_out;
    int n = in_sizes[0] / 8;

    void* cnt_addr = nullptr;
    cudaGetSymbolAddress(&cnt_addr, g_count);
    cudaMemsetAsync(cnt_addr, 0, sizeof(int));

    int threads = 128;
    int items_per_block = threads * 2;
    int blocks = (n + items_per_block - 1) / items_per_block;
    pass1_f32x2_kernel<<<blocks, threads>>>(lie, out, n);
    pass2_coop_kernel<<<1024, 64>>>(lie, out);
}

// round 15
// speedup vs baseline: 1.3420x; 1.0052x over previous
#include <cuda_runtime.h>
#include <math.h>

// Hybrid-precision batched expm of sl(3) elements.
//   Pass 1 (fp32, PACKED f32x2): two batch items per thread via fma.rn.f32x2.
//     Fixed scaling s=3, PS degree-11 Taylor, 3 squarings. Flags untrusted
//     samples via warp-aggregated atomics (single atomic per warp).
//     Smem-staged scalar coalesced stores. rcp.approx for normalization.
//   Pass 2 (df64, 3-lane cooperative): one matrix row per lane, shuffle-based
//     3x3 df64 matmuls, fixed s=5, straight-line.

#define MAXB (1 << 20)
#define TAU 262144.0f
__device__ int g_count;
__device__ int g_flag_idx[MAXB];

typedef unsigned long long u64;

// ---------------- packed f32x2 helpers (pass 1) ----------------
__device__ __forceinline__ u64 pk2(float lo, float hi) {
    u64 r;
    asm("mov.b64 %0, {%1, %2};" : "=l"(r) : "f"(lo), "f"(hi));
    return r;
}
__device__ __forceinline__ void upk2(u64 v, float& lo, float& hi) {
    asm("mov.b64 {%0, %1}, %2;" : "=f"(lo), "=f"(hi) : "l"(v));
}
__device__ __forceinline__ u64 fma2(u64 a, u64 b, u64 c) {
    u64 d;
    asm("fma.rn.f32x2 %0, %1, %2, %3;" : "=l"(d) : "l"(a), "l"(b), "l"(c));
    return d;
}
__device__ __forceinline__ u64 mul2(u64 a, u64 b) {
    u64 d;
    asm("mul.rn.f32x2 %0, %1, %2;" : "=l"(d) : "l"(a), "l"(b));
    return d;
}
__device__ __forceinline__ u64 add2(u64 a, u64 b) {
    u64 d;
    asm("add.rn.f32x2 %0, %1, %2;" : "=l"(d) : "l"(a), "l"(b));
    return d;
}
__device__ __forceinline__ float frcp_approx(float x) {
    float r;
    asm("rcp.approx.f32 %0, %1;" : "=f"(r) : "f"(x));
    return r;
}

__device__ __forceinline__ void mm3p(const u64* __restrict__ a,
                                     const u64* __restrict__ b,
                                     u64* __restrict__ c) {
#pragma unroll
    for (int i = 0; i < 3; i++)
#pragma unroll
        for (int j = 0; j < 3; j++) {
            u64 s = mul2(a[i * 3], b[j]);
            s = fma2(a[i * 3 + 1], b[3 + j], s);
            s = fma2(a[i * 3 + 2], b[6 + j], s);
            c[i * 3 + j] = s;
        }
}

// ---------------- df64 (double-float) arithmetic (pass 2) ----------------
struct df { float h, l; };

__device__ __forceinline__ df two_sum(float a, float b) {
    float s = a + b;
    float bb = s - a;
    float e = (a - (s - bb)) + (b - bb);
    df r; r.h = s; r.l = e; return r;
}
__device__ __forceinline__ df quick2(float a, float b) {  // |a| >= |b|
    float s = a + b;
    float e = b - (s - a);
    df r; r.h = s; r.l = e; return r;
}
__device__ __forceinline__ df df_add(df a, df b) {
    df s = two_sum(a.h, b.h);
    s.l += (a.l + b.l);
    return quick2(s.h, s.l);
}
__device__ __forceinline__ df df_mul(df a, df b) {
    float p = a.h * b.h;
    float e = fmaf(a.h, b.h, -p);
    e = fmaf(a.h, b.l, fmaf(a.l, b.h, e));
    return quick2(p, e);
}
__device__ __forceinline__ df df_scale_pow2(df a, float p2) {
    df r; r.h = a.h * p2; r.l = a.l * p2; return r;
}
__device__ __forceinline__ df df_neg(df a) { df r; r.h = -a.h; r.l = -a.l; return r; }

#define DFC(x) df{(float)(x), (float)((x) - (double)(float)(x))}

// Compensated 3-term df dot product.
__device__ __forceinline__ df dot3(df a0, df b0, df a1, df b1, df a2, df b2) {
    float p1 = a0.h * b0.h;
    float e1 = fmaf(a0.h, b0.h, -p1);
    e1 = fmaf(a0.h, b0.l, fmaf(a0.l, b0.h, e1));
    float p2 = a1.h * b1.h;
    float e2 = fmaf(a1.h, b1.h, -p2);
    e2 = fmaf(a1.h, b1.l, fmaf(a1.l, b1.h, e2));
    float p3 = a2.h * b2.h;
    float e3 = fmaf(a2.h, b2.h, -p3);
    e3 = fmaf(a2.h, b2.l, fmaf(a2.l, b2.h, e3));

    df s1 = two_sum(p1, p2);
    df s2 = two_sum(s1.h, p3);
    float e = ((e1 + e2) + (e3 + s1.l)) + s2.l;
    return quick2(s2.h, e);
}

__device__ __forceinline__ df shfl_df(df v, int src) {
    df r;
    r.h = __shfl_sync(0xFFFFFFFFu, v.h, src);
    r.l = __shfl_sync(0xFFFFFFFFu, v.l, src);
    return r;
}

// Cooperative 3x3 df matmul: 3 lanes per item, lane holds one row.
__device__ __forceinline__ void coop_mm(df& c0, df& c1, df& c2,
                                        df a0, df a1, df a2,
                                        df y0, df y1, df y2, int base) {
    df Y00 = shfl_df(y0, base),     Y01 = shfl_df(y1, base),     Y02 = shfl_df(y2, base);
    df Y10 = shfl_df(y0, base + 1), Y11 = shfl_df(y1, base + 1), Y12 = shfl_df(y2, base + 1);
    df Y20 = shfl_df(y0, base + 2), Y21 = shfl_df(y1, base + 2), Y22 = shfl_df(y2, base + 2);
    c0 = dot3(a0, Y00, a1, Y10, a2, Y20);
    c1 = dot3(a0, Y01, a1, Y11, a2, Y21);
    c2 = dot3(a0, Y02, a1, Y12, a2, Y22);
}

__device__ __forceinline__ void expm_coop(const float* __restrict__ lie,
                                          float* __restrict__ out,
                                          int idx, int role, int base,
                                          bool active) {
    const float4* vp = reinterpret_cast<const float4*>(lie) + 2 * (size_t)idx;
    float4 v0 = vp[0];
    float4 v1 = vp[1];
    float x = v0.x, y = v0.y, r = v0.z, sc = v0.w;
    float st = v1.x, sh = v1.y, kx = v1.z, ky = v1.w;

    float u0, w0, u1, w1, u2, w2;
    if (role == 0)      { u0 = sc; w0 = st;  u1 = sh; w1 = -r;  u2 = x;           w2 = 0.f; }
    else if (role == 1) { u0 = sh; w0 = r;   u1 = sc; w1 = -st; u2 = y;           w2 = 0.f; }
    else                { u0 = kx; w0 = 0.f; u1 = ky; w1 = 0.f; u2 = -2.0f * sc;  w2 = 0.f; }

    const float SCL = 0.03125f;  // 2^-5 (fixed s = 5; nrm <= 32 guaranteed)
    df A0 = df_scale_pow2(two_sum(u0, w0), SCL);
    df A1 = df_scale_pow2(two_sum(u1, w1), SCL);
    df A2 = df_scale_pow2(two_sum(u2, w2), SCL);

    df B0, B1, B2;  // row of A^2
    coop_mm(B0, B1, B2, A0, A1, A2, A0, A1, A2, base);
    df Z0, Z1, Z2;  // row of A^3
    coop_mm(Z0, Z1, Z2, B0, B1, B2, A0, A1, A2, base);

    const df C2  = DFC(1.0 / 2.0);
    const df C3  = DFC(1.0 / 6.0);
    const df C4  = DFC(1.0 / 24.0);
    const df C5  = DFC(1.0 / 120.0);
    const df C6  = DFC(1.0 / 720.0);
    const df C7  = DFC(1.0 / 5040.0);
    const df C8  = DFC(1.0 / 40320.0);
    const df C9  = DFC(1.0 / 362880.0);
    const df C10 = DFC(1.0 / 3628800.0);
    const df C11 = DFC(1.0 / 39916800.0);
    const df ONE = df{1.0f, 0.0f};

    df P0, P1, P2, T0, T1, T2;

    P0 = df_add(df_mul(C10, A0), df_mul(C11, B0));
    P1 = df_add(df_mul(C10, A1), df_mul(C11, B1));
    P2 = df_add(df_mul(C10, A2), df_mul(C11, B2));
    if (role == 0) P0 = df_add(P0, C9);
    else if (role == 1) P1 = df_add(P1, C9);
    else P2 = df_add(P2, C9);

    coop_mm(T0, T1, T2, P0, P1, P2, Z0, Z1, Z2, base);
    P0 = df_add(T0, df_add(df_mul(C7, A0), df_mul(C8, B0)));
    P1 = df_add(T1, df_add(df_mul(C7, A1), df_mul(C8, B1)));
    P2 = df_add(T2, df_add(df_mul(C7, A2), df_mul(C8, B2)));
    if (role == 0) P0 = df_add(P0, C6);
    else if (role == 1) P1 = df_add(P1, C6);
    else P2 = df_add(P2, C6);

    coop_mm(T0, T1, T2, P0, P1, P2, Z0, Z1, Z2, base);
    P0 = df_add(T0, df_add(df_mul(C4, A0), df_mul(C5, B0)));
    P1 = df_add(T1, df_add(df_mul(C4, A1), df_mul(C5, B1)));
    P2 = df_add(T2, df_add(df_mul(C4, A2), df_mul(C5, B2)));
    if (role == 0) P0 = df_add(P0, C3);
    else if (role == 1) P1 = df_add(P1, C3);
    else P2 = df_add(P2, C3);

    coop_mm(T0, T1, T2, P0, P1, P2, Z0, Z1, Z2, base);
    P0 = df_add(T0, df_add(A0, df_mul(C2, B0)));
    P1 = df_add(T1, df_add(A1, df_mul(C2, B1)));
    P2 = df_add(T2, df_add(A2, df_mul(C2, B2)));
    if (role == 0) P0 = df_add(P0, ONE);
    else if (role == 1) P1 = df_add(P1, ONE);
    else P2 = df_add(P2, ONE);

#pragma unroll
    for (int q = 0; q < 5; q++) {
        coop_mm(T0, T1, T2, P0, P1, P2, P0, P1, P2, base);
        P0 = T0; P1 = T1; P2 = T2;
    }

    df p22 = shfl_df(P2, base + 2);

    float approx = frcp_approx(p22.h);
    df e = df_mul(p22, df{approx, 0.f});
    df corr = df_add(df{2.0f, 0.0f}, df_neg(e));
    df rcp = df_mul(corr, df{approx, 0.f});

    if (active) {
        float* o = out + 9 * (size_t)idx + 3 * role;
        df q0 = df_mul(P0, rcp);
        df q1 = df_mul(P1, rcp);
        df q2 = df_mul(P2, rcp);
        o[0] = q0.h + q0.l;
        o[1] = q1.h + q1.l;
        o[2] = q2.h + q2.l;
    }
}

// ---------------- fp32 packed fast path ----------------
__global__ void __launch_bounds__(128)
pass1_f32x2_kernel(const float* __restrict__ lie, float* __restrict__ out, int n) {
    __shared__ float stage[128 * 18];

    int t = blockIdx.x * blockDim.x + threadIdx.x;
    int lane = threadIdx.x & 31;
    int warp = threadIdx.x >> 5;
    long long i0 = 2LL * t;
    long long i1 = i0 + 1;
    bool vlo = (i0 < n), vhi = (i1 < n);

    float4 a0 = make_float4(0.f, 0.f, 0.f, 0.f), a1 = a0, b0 = a0, b1 = a0;
    if (vlo) {
        const float4* vp = reinterpret_cast<const float4*>(lie) + 2 * i0;
        a0 = vp[0]; a1 = vp[1];
    }
    if (vhi) {
        const float4* vp = reinterpret_cast<const float4*>(lie) + 2 * i1;
        b0 = vp[0]; b1 = vp[1];
    }

    const float SCL = 0.125f;  // fixed s = 3

    float AL[9], AH[9];
    AL[0] = (a0.w + a1.x) * SCL; AL[1] = (a1.y - a0.z) * SCL; AL[2] = a0.x * SCL;
    AL[3] = (a1.y + a0.z) * SCL; AL[4] = (a0.w - a1.x) * SCL; AL[5] = a0.y * SCL;
    AL[6] = a1.z * SCL;          AL[7] = a1.w * SCL;          AL[8] = -2.0f * a0.w * SCL;

    AH[0] = (b0.w + b1.x) * SCL; AH[1] = (b1.y - b0.z) * SCL; AH[2] = b0.x * SCL;
    AH[3] = (b1.y + b0.z) * SCL; AH[4] = (b0.w - b1.x) * SCL; AH[5] = b0.y * SCL;
    AH[6] = b1.z * SCL;          AH[7] = b1.w * SCL;          AH[8] = -2.0f * b0.w * SCL;

    float nl = fmaxf(fabsf(AL[0]) + fabsf(AL[1]) + fabsf(AL[2]),
               fmaxf(fabsf(AL[3]) + fabsf(AL[4]) + fabsf(AL[5]),
                     fabsf(AL[6]) + fabsf(AL[7]) + fabsf(AL[8])));
    float nh = fmaxf(fabsf(AH[0]) + fabsf(AH[1]) + fabsf(AH[2]),
               fmaxf(fabsf(AH[3]) + fabsf(AH[4]) + fabsf(AH[5]),
                     fabsf(AH[6]) + fabsf(AH[7]) + fabsf(AH[8])));

    u64 A[9];
#pragma unroll
    for (int k = 0; k < 9; k++) A[k] = pk2(AL[k], AH[k]);

    u64 A2[9], A3[9];
    mm3p(A, A, A2);
    mm3p(A2, A, A3);

    const u64 C2  = pk2(1.0f / 2, 1.0f / 2);
    const u64 C3  = pk2(1.0f / 6, 1.0f / 6);
    const u64 C4  = pk2(1.0f / 24, 1.0f / 24);
    const u64 C5  = pk2(1.0f / 120, 1.0f / 120);
    const u64 C6  = pk2(1.0f / 720, 1.0f / 720);
    const u64 C7  = pk2(1.0f / 5040, 1.0f / 5040);
    const u64 C8  = pk2(1.0f / 40320, 1.0f / 40320);
    const u64 C9  = pk2(1.0f / 362880, 1.0f / 362880);
    const u64 C10 = pk2(1.0f / 3628800, 1.0f / 3628800);
    const u64 C11 = pk2(1.0f / 39916800, 1.0f / 39916800);
    const u64 ONE = pk2(1.0f, 1.0f);

    u64 P[9], T[9];
#pragma unroll
    for (int k = 0; k < 9; k++) P[k] = fma2(C10, A[k], mul2(C11, A2[k]));
    P[0] = add2(P[0], C9); P[4] = add2(P[4], C9); P[8] = add2(P[8], C9);

    mm3p(P, A3, T);
#pragma unroll
    for (int k = 0; k < 9; k++) P[k] = fma2(C7, A[k], fma2(C8, A2[k], T[k]));
    P[0] = add2(P[0], C6); P[4] = add2(P[4], C6); P[8] = add2(P[8], C6);

    mm3p(P, A3, T);
#pragma unroll
    for (int k = 0; k < 9; k++) P[k] = fma2(C4, A[k], fma2(C5, A2[k], T[k]));
    P[0] = add2(P[0], C3); P[4] = add2(P[4], C3); P[8] = add2(P[8], C3);

    mm3p(P, A3, T);
#pragma unroll
    for (int k = 0; k < 9; k++) P[k] = fma2(C2, A2[k], add2(T[k], A[k]));
    P[0] = add2(P[0], ONE); P[4] = add2(P[4], ONE); P[8] = add2(P[8], ONE);

    mm3p(P, P, T);
    mm3p(T, T, P);
    mm3p(P, P, T);

    float HL[9], HH[9];
#pragma unroll
    for (int k = 0; k < 9; k++) upk2(T[k], HL[k], HH[k]);

    float mxl = 0.0f, mxh = 0.0f;
#pragma unroll
    for (int k = 0; k < 9; k++) {
        mxl = fmaxf(mxl, fabsf(HL[k]));
        mxh = fmaxf(mxh, fabsf(HH[k]));
    }
    bool flag_lo = vlo && !((nl <= 2.0f) && (8.0f * mxl <= TAU * fabsf(HL[8])));
    bool flag_hi = vhi && !((nh <= 2.0f) && (8.0f * mxh <= TAU * fabsf(HH[8])));

    // Warp-aggregated compaction: ONE atomic per warp for lo+hi combined.
    unsigned blo = __ballot_sync(0xFFFFFFFFu, flag_lo);
    unsigned bhi = __ballot_sync(0xFFFFFFFFu, flag_hi);
    if (blo | bhi) {
        int nlo = __popc(blo);
        int base = 0;
        if (lane == 0) base = atomicAdd(&g_count, nlo + __popc(bhi));
        base = __shfl_sync(0xFFFFFFFFu, base, 0);
        unsigned below = (1u << lane) - 1u;
        if (flag_lo) {
            int slot = base + __popc(blo & below);
            if (slot < MAXB) g_flag_idx[slot] = (int)i0;
        }
        if (flag_hi) {
            int slot = base + nlo + __popc(bhi & below);
            if (slot < MAXB) g_flag_idx[slot] = (int)i1;
        }
    }

    float invl = frcp_approx(HL[8]);
    float invh = frcp_approx(HH[8]);
    float* ws = stage + warp * 576;
#pragma unroll
    for (int k = 0; k < 9; k++) {
        ws[lane * 18 + k] = HL[k] * invl;
        ws[lane * 18 + 9 + k] = HH[k] * invh;
    }
    __syncwarp();

    long long wstart = 2LL * ((long long)blockIdx.x * blockDim.x + warp * 32);
    long long rem = (long long)n - wstart;
    int vcount = (rem > 64) ? 64 : (rem > 0 ? (int)rem : 0);
    if (vcount > 0) {
        float* o = out + 9 * wstart;
        int total = vcount * 9;
        for (int j = lane; j < total; j += 32) o[j] = ws[j];
    }
}

__global__ void __launch_bounds__(64)
pass2_coop_kernel(const float* __restrict__ lie, float* __restrict__ out) {
    int cnt = g_count;
    if (cnt > MAXB) cnt = MAXB;

    int lane = threadIdx.x & 31;
    int grp = lane / 3;            // 0..9 active groups; grp==10 idle (lanes 30,31)
    int role = lane - grp * 3;
    int base = grp * 3;

    int wpb = blockDim.x >> 5;
    int gwarp = blockIdx.x * wpb + (threadIdx.x >> 5);
    int nwarp = gridDim.x * wpb;

    for (int it0 = gwarp * 10; it0 < cnt; it0 += nwarp * 10) {
        int item = it0 + grp;
        bool active = (grp < 10) && (item < cnt);
        int idx = active ? g_flag_idx[item] : 0;
        expm_coop(lie, out, idx, role, base, active);
    }
}

extern "C" void kernel_launch(void* const* d_in, const int* in_sizes, int n_in,
                              void* d_out, int out_size) {
    const float* lie = (const float*)d_in[0];
    float* out = (float*)d_out;
    int n = in_sizes[0] / 8;

    void* cnt_addr = nullptr;
    cudaGetSymbolAddress(&cnt_addr, g_count);
    cudaMemsetAsync(cnt_addr, 0, sizeof(int));

    int threads = 128;
    int items_per_block = threads * 2;
    int blocks = (n + items_per_block - 1) / items_per_block;
    pass1_f32x2_kernel<<<blocks, threads>>>(lie, out, n);
    pass2_coop_kernel<<<1024, 64>>>(lie, out);
}